// round 2
// baseline (speedup 1.0000x reference)
#include <cuda_runtime.h>
#include <math.h>

#define NT 512
#define PI_D 3.14159265358979323846

// ---------------- static device scratch ----------------
__device__ float2 g_S[512 * 2 * 128 * 128];   // state [b][f][X][Y], 134 MB
__device__ float4 g_U0[128 * 128 * 2];        // mux0 unitaries, bitrev-permuted (2 float4 per entry)
__device__ float4 g_U1[2 * 2 * 64 * 64 * 2];
__device__ float4 g_U2[2 * 2 * 32 * 32 * 2];
__device__ float2 g_TW[64];                   // exp(-2*pi*i*t/128)
__device__ int    g_NR[128];                  // bitrev-domain negation table

// ---------------- generic batched smem FFT ----------------
// element (line, p) lives at base[p*sp + (line&lmask)*sl1 + (line>>l1b)*sl2]
// FWD: DIF, natural->bitrev, twiddle exp(-2pi i t/2^{s+1})
// INV: DIT, bitrev->natural, conj twiddle, scale folded into last stage
template<bool INV>
__device__ __forceinline__ void do_fft(float2* base, const float2* tw, int sp,
                                       int sl1, int lmask, int l1b, int sl2,
                                       int nl_log, int logn, float scale) {
    const int nbf = 1 << (nl_log + logn - 1);
    for (int si = 0; si < logn; ++si) {
        const int s = INV ? si : (logn - 1 - si);
        const int h = 1 << s;
        const bool last = INV && (si == logn - 1);
        for (int u = threadIdx.x; u < nbf; u += NT) {
            const int line = u & ((1 << nl_log) - 1);
            const int v = u >> nl_log;
            const int t = v & (h - 1);
            const int p = ((v >> s) << (s + 1)) + t;
            const int loff = (line & lmask) * sl1 + (line >> l1b) * sl2;
            float2* a0 = base + p * sp + loff;
            float2* a1 = base + (p + h) * sp + loff;
            const float2 w = tw[t << (6 - s)];
            float2 x = *a0, y = *a1;
            if (!INV) {
                float2 d = make_float2(x.x - y.x, x.y - y.y);
                *a0 = make_float2(x.x + y.x, x.y + y.y);
                *a1 = make_float2(d.x * w.x - d.y * w.y, d.x * w.y + d.y * w.x);
            } else {
                float2 yw = make_float2(y.x * w.x + y.y * w.y, y.y * w.x - y.x * w.y);
                float2 r0 = make_float2(x.x + yw.x, x.y + yw.y);
                float2 r1 = make_float2(x.x - yw.x, x.y - yw.y);
                if (last) { r0.x *= scale; r0.y *= scale; r1.x *= scale; r1.y *= scale; }
                *a0 = r0; *a1 = r1;
            }
        }
        __syncthreads();
    }
}

__device__ __forceinline__ void apply_mux(float2& p0, float2& p1, float4 uA, float4 uB) {
    // uA = (u00.x,u00.y,u01.x,u01.y), uB = (u10.x,u10.y,u11.x,u11.y)
    float2 o0, o1;
    o0.x = uA.x * p0.x - uA.y * p0.y + uA.z * p1.x - uA.w * p1.y;
    o0.y = uA.x * p0.y + uA.y * p0.x + uA.z * p1.y + uA.w * p1.x;
    o1.x = uB.x * p0.x - uB.y * p0.y + uB.z * p1.x - uB.w * p1.y;
    o1.y = uB.x * p0.y + uB.y * p0.x + uB.z * p1.y + uB.w * p1.x;
    p0 = o0; p1 = o1;
}

// ---------------- K0: precompute ----------------
__device__ __forceinline__ void writeU(float4* dst, float axf, float ayf, float azf) {
    double ax = axf, ay = ayf, az = azf;
    double r = sqrt(ax * ax + ay * ay + az * az + 1e-20);
    double cr = cos(r), sn = sin(r) / r;
    // u00 = cr - i az sn; u01 = (-ay - i ax) sn; u10 = (ay - i ax) sn; u11 = cr + i az sn
    dst[0] = make_float4((float)cr, (float)(-az * sn), (float)(-ay * sn), (float)(-ax * sn));
    dst[1] = make_float4((float)(ay * sn), (float)(-ax * sn), (float)cr, (float)(az * sn));
}

__global__ void k0(const float* __restrict__ mux0, const float* __restrict__ mux1,
                   const float* __restrict__ mux2) {
    int idx = blockIdx.x * blockDim.x + threadIdx.x;   // 64*256 = 16384 threads
    if (idx < 64) {
        double ang = -2.0 * PI_D * (double)idx / 128.0;
        g_TW[idx] = make_float2((float)cos(ang), (float)sin(ang));
    }
    if (idx < 128) {
        int k = __brev((unsigned)idx) >> 25;
        g_NR[idx] = (int)(__brev((unsigned)((128 - k) & 127)) >> 25);
    }
    {   // U0: [128][128], both axes rev7
        int kxb = idx >> 7, kyb = idx & 127;
        int kx = __brev((unsigned)kxb) >> 25, ky = __brev((unsigned)kyb) >> 25;
        const float* c = mux0 + (kx * 128 + ky) * 3;
        writeU(&g_U0[idx * 2], c[0], c[1], c[2]);
    }
    {   // U1: [2][2][64][64], rev6
        int cx = idx >> 13, cy = (idx >> 12) & 1, kxb = (idx >> 6) & 63, kyb = idx & 63;
        int kx = __brev((unsigned)kxb) >> 26, ky = __brev((unsigned)kyb) >> 26;
        const float* c = mux1 + (((cx * 2 + cy) * 64 + kx) * 64 + ky) * 3;
        writeU(&g_U1[idx * 2], c[0], c[1], c[2]);
    }
    if (idx < 4096) {   // U2: [2][2][32][32], rev5
        int cx = idx >> 11, cy = (idx >> 10) & 1, kxb = (idx >> 5) & 31, kyb = idx & 31;
        int kx = __brev((unsigned)kxb) >> 27, ky = __brev((unsigned)kyb) >> 27;
        const float* c = mux2 + (((cx * 2 + cy) * 32 + kx) * 32 + ky) * 3;
        writeU(&g_U2[idx * 2], c[0], c[1], c[2]);
    }
}

// ---------------- P1: encode + y-FFT128 (Hermitian packed) ----------------
// CTA: (chunk of 32 X rows, b). smem z[128 pos][33] (pad), lines = 32 rows.
__global__ __launch_bounds__(NT) void p1(const float* __restrict__ images) {
    extern __shared__ char sm[];
    float2* z = (float2*)sm;                       // 128*33 float2
    float2* tw = (float2*)(sm + 128 * 33 * 8);
    const int b = blockIdx.y, X0 = blockIdx.x * 32;
    for (int i = threadIdx.x; i < 64; i += NT) tw[i] = g_TW[i];
    for (int idx = threadIdx.x; idx < 4096; idx += NT) {
        int l = idx >> 7, y = idx & 127;
        float I = images[(b * 128 + X0 + l) * 128 + y];
        float sv, cv;
        sincosf(0.5f * (float)PI_D * I, &sv, &cv);
        z[y * 33 + l] = make_float2(cv * (1.0f / 128.0f), sv * (1.0f / 128.0f));
    }
    __syncthreads();
    do_fft<false>(z, tw, 33, 1, 31, 5, 0, 5, 7, 1.f);
    // unpack Hermitian pair -> f0 (cos plane), f1 (sin plane), store bitrev-y spectra
    for (int idx = threadIdx.x; idx < 4096; idx += NT) {
        int l = idx >> 7, kb = idx & 127;
        float2 Z = z[kb * 33 + l];
        float2 Zn = z[g_NR[kb] * 33 + l];
        float2 C = make_float2(0.5f * (Z.x + Zn.x), 0.5f * (Z.y - Zn.y));
        float2 Sf = make_float2(0.5f * (Z.y + Zn.y), 0.5f * (Zn.x - Z.x));
        int X = X0 + l;
        g_S[((b * 2 + 0) * 128 + X) * 128 + kb] = C;
        g_S[((b * 2 + 1) * 128 + X) * 128 + kb] = Sf;
    }
}

// ---------------- P2: x-FFT128 + mux0 + x-IFFT128 + x-FFT64(halves) ----------------
// CTA: (y chunk of 16, b). tile [2 f][128 X][16 yl]
__global__ __launch_bounds__(NT) void p2() {
    extern __shared__ char sm[];
    float2* tile = (float2*)sm;                    // 2*128*16
    float2* tw = (float2*)(sm + 2 * 128 * 16 * 8);
    const int b = blockIdx.y, y0 = blockIdx.x * 16;
    for (int i = threadIdx.x; i < 64; i += NT) tw[i] = g_TW[i];
    for (int idx = threadIdx.x; idx < 4096; idx += NT) {
        int yl = idx & 15, X = (idx >> 4) & 127, f = idx >> 11;
        tile[f * 2048 + X * 16 + yl] = g_S[((b * 2 + f) * 128 + X) * 128 + y0 + yl];
    }
    __syncthreads();
    do_fft<false>(tile, tw, 16, 1, 15, 4, 2048, 5, 7, 1.f);
    for (int idx = threadIdx.x; idx < 2048; idx += NT) {
        int yl = idx & 15, kxb = idx >> 4;
        int off = kxb * 16 + yl;
        float2 p0v = tile[off], p1v = tile[2048 + off];
        int ui = ((kxb << 7) + y0 + yl) * 2;
        apply_mux(p0v, p1v, g_U0[ui], g_U0[ui + 1]);
        tile[off] = p0v; tile[2048 + off] = p1v;
    }
    __syncthreads();
    do_fft<true>(tile, tw, 16, 1, 15, 4, 2048, 5, 7, 1.0f / 128.0f);
    do_fft<false>(tile,        tw, 16, 1, 15, 4, 2048, 5, 6, 1.f);
    do_fft<false>(tile + 1024, tw, 16, 1, 15, 4, 2048, 5, 6, 1.f);
    for (int idx = threadIdx.x; idx < 4096; idx += NT) {
        int yl = idx & 15, X = (idx >> 4) & 127, f = idx >> 11;
        g_S[((b * 2 + f) * 128 + X) * 128 + y0 + yl] = tile[f * 2048 + X * 16 + yl];
    }
}

// ---------------- P3: y-IFFT128 + y-FFT64(halves) ----------------
// CTA: (X chunk of 16, b). tile [2 f][128 y][17] (pad)
__global__ __launch_bounds__(NT) void p3() {
    extern __shared__ char sm[];
    float2* tile = (float2*)sm;                    // 2*128*17
    float2* tw = (float2*)(sm + 2 * 128 * 17 * 8);
    const int b = blockIdx.y, X0 = blockIdx.x * 16;
    for (int i = threadIdx.x; i < 64; i += NT) tw[i] = g_TW[i];
    for (int idx = threadIdx.x; idx < 4096; idx += NT) {
        int y = idx & 127, xl = (idx >> 7) & 15, f = idx >> 11;
        tile[f * 2176 + y * 17 + xl] = g_S[((b * 2 + f) * 128 + X0 + xl) * 128 + y];
    }
    __syncthreads();
    do_fft<true>(tile, tw, 17, 1, 15, 4, 2176, 5, 7, 1.0f / 128.0f);
    do_fft<false>(tile,        tw, 17, 1, 15, 4, 2176, 5, 6, 1.f);
    do_fft<false>(tile + 1088, tw, 17, 1, 15, 4, 2176, 5, 6, 1.f);
    for (int idx = threadIdx.x; idx < 4096; idx += NT) {
        int y = idx & 127, xl = (idx >> 7) & 15, f = idx >> 11;
        g_S[((b * 2 + f) * 128 + X0 + xl) * 128 + y] = tile[f * 2176 + y * 17 + xl];
    }
}

// ---------------- P4: mux1 + x-junction64 + y-junction64 + mux2 (64x64 block) ----------------
// CTA: (xc1*2+yc1, b). tile [2 f][64 X'][65] (pad)
__global__ __launch_bounds__(NT) void p4() {
    extern __shared__ char sm[];
    float2* tile = (float2*)sm;                    // 2*64*65
    float2* tw = (float2*)(sm + 2 * 64 * 65 * 8);
    const int b = blockIdx.y;
    const int xc1 = blockIdx.x >> 1, yc1 = blockIdx.x & 1;
    for (int i = threadIdx.x; i < 64; i += NT) tw[i] = g_TW[i];
    for (int idx = threadIdx.x; idx < 8192; idx += NT) {
        int Yp = idx & 63, Xp = (idx >> 6) & 63, f = idx >> 12;
        tile[f * 4160 + Xp * 65 + Yp] =
            g_S[((b * 2 + f) * 128 + xc1 * 64 + Xp) * 128 + yc1 * 64 + Yp];
    }
    __syncthreads();
    for (int idx = threadIdx.x; idx < 4096; idx += NT) {     // mux1
        int Yp = idx & 63, Xp = idx >> 6;
        int off = Xp * 65 + Yp;
        float2 p0v = tile[off], p1v = tile[4160 + off];
        int ui = (((xc1 * 2 + yc1) << 12) + (Xp << 6) + Yp) * 2;
        apply_mux(p0v, p1v, g_U1[ui], g_U1[ui + 1]);
        tile[off] = p0v; tile[4160 + off] = p1v;
    }
    __syncthreads();
    // x-direction: ifft64, fft32 halves (pos = X', sp=65; lines = (Y', f))
    do_fft<true>(tile, tw, 65, 1, 63, 6, 4160, 7, 6, 1.0f / 64.0f);
    do_fft<false>(tile,           tw, 65, 1, 63, 6, 4160, 7, 5, 1.f);
    do_fft<false>(tile + 32 * 65, tw, 65, 1, 63, 6, 4160, 7, 5, 1.f);
    // y-direction (pos = Y', sp=1; lines = (X', f))
    do_fft<true>(tile, tw, 1, 65, 63, 6, 4160, 7, 6, 1.0f / 64.0f);
    do_fft<false>(tile,      tw, 1, 65, 63, 6, 4160, 7, 5, 1.f);
    do_fft<false>(tile + 32, tw, 1, 65, 63, 6, 4160, 7, 5, 1.f);
    for (int idx = threadIdx.x; idx < 4096; idx += NT) {     // mux2
        int Yp = idx & 63, Xp = idx >> 6;
        int off = Xp * 65 + Yp;
        float2 p0v = tile[off], p1v = tile[4160 + off];
        int ui = ((((Xp >> 5) * 2 + (Yp >> 5)) << 10) + ((Xp & 31) << 5) + (Yp & 31)) * 2;
        apply_mux(p0v, p1v, g_U2[ui], g_U2[ui + 1]);
        tile[off] = p0v; tile[4160 + off] = p1v;
    }
    __syncthreads();
    for (int idx = threadIdx.x; idx < 8192; idx += NT) {
        int Yp = idx & 63, Xp = (idx >> 6) & 63, f = idx >> 12;
        g_S[((b * 2 + f) * 128 + xc1 * 64 + Xp) * 128 + yc1 * 64 + Yp] =
            tile[f * 4160 + Xp * 65 + Yp];
    }
}

// ---------------- P5: x-IFFT32 + y-IFFT32 + measure + GEMV ----------------
// CTA per b. tile [2 f][32 x'][129] (pad), prob[32][32][2] f32
__global__ __launch_bounds__(NT) void p5(const float* __restrict__ W,
                                         const float* __restrict__ bias,
                                         float* __restrict__ out) {
    extern __shared__ char sm[];
    float2* tile = (float2*)sm;                         // 2*32*129 = 8256 f2
    float* prob = (float*)(sm + 8256 * 8);              // 2048 f32
    float2* tw = (float2*)(sm + 8256 * 8 + 8192);
    float* red = (float*)(sm + 8256 * 8 + 8192 + 512);  // 160 f32
    const int b = blockIdx.x;
    for (int i = threadIdx.x; i < 64; i += NT) tw[i] = g_TW[i];
    for (int i = threadIdx.x; i < 2048; i += NT) prob[i] = 0.f;
    __syncthreads();
    for (int xc = 0; xc < 4; ++xc) {
        for (int idx = threadIdx.x; idx < 8192; idx += NT) {
            int y = idx & 127, xp = (idx >> 7) & 31, f = idx >> 12;
            tile[f * 4128 + xp * 129 + y] = g_S[((b * 2 + f) * 128 + xc * 32 + xp) * 128 + y];
        }
        __syncthreads();
        // x ifft32: pos = x' (sp=129), lines = (y, f)
        do_fft<true>(tile, tw, 129, 1, 127, 7, 4128, 8, 5, 1.0f / 32.0f);
        // y ifft32 per y-segment: pos = y' (sp=1), lines = (x', f)
        for (int ys = 0; ys < 4; ++ys)
            do_fft<true>(tile + ys * 32, tw, 1, 129, 31, 5, 4128, 6, 5, 1.0f / 32.0f);
        // accumulate probabilities (each thread owns cells -> deterministic)
        for (int idx = threadIdx.x; idx < 2048; idx += NT) {
            int f = idx & 1, yp = (idx >> 1) & 31, xp = idx >> 6;
            float s = 0.f;
            #pragma unroll
            for (int ys = 0; ys < 4; ++ys) {
                float2 v = tile[f * 4128 + xp * 129 + ys * 32 + yp];
                s += v.x * v.x + v.y * v.y;
            }
            prob[idx] += s;
        }
        __syncthreads();
    }
    // GEMV: logits[c] = bias[c] + sum_j prob[j] * W[c][j], j = (xa*32+ya)*2+f
    float acc[10];
    #pragma unroll
    for (int c = 0; c < 10; ++c) acc[c] = 0.f;
    const int j0 = threadIdx.x * 4;
    float4 pv = *(const float4*)(prob + j0);
    #pragma unroll
    for (int c = 0; c < 10; ++c) {
        float4 wv = *(const float4*)(W + c * 2048 + j0);
        acc[c] += pv.x * wv.x + pv.y * wv.y + pv.z * wv.z + pv.w * wv.w;
    }
    #pragma unroll
    for (int c = 0; c < 10; ++c)
        for (int off = 16; off > 0; off >>= 1)
            acc[c] += __shfl_down_sync(0xffffffffu, acc[c], off);
    const int warp = threadIdx.x >> 5, lane = threadIdx.x & 31;
    if (lane == 0)
        #pragma unroll
        for (int c = 0; c < 10; ++c) red[warp * 10 + c] = acc[c];
    __syncthreads();
    if (threadIdx.x < 10) {
        float s = bias[threadIdx.x];
        #pragma unroll
        for (int w = 0; w < 16; ++w) s += red[w * 10 + threadIdx.x];
        out[b * 10 + threadIdx.x] = s;
    }
}

// ---------------- launch ----------------
#define P1_SMEM (128 * 33 * 8 + 512)
#define P2_SMEM (2 * 128 * 16 * 8 + 512)
#define P3_SMEM (2 * 128 * 17 * 8 + 512)
#define P4_SMEM (2 * 64 * 65 * 8 + 512)
#define P5_SMEM (8256 * 8 + 8192 + 512 + 640)

extern "C" void kernel_launch(void* const* d_in, const int* in_sizes, int n_in,
                              void* d_out, int out_size) {
    const float* images = (const float*)d_in[0];
    const float* mux0 = (const float*)d_in[1];
    const float* mux1 = (const float*)d_in[2];
    const float* mux2 = (const float*)d_in[3];
    const float* W = (const float*)d_in[4];
    const float* bias = (const float*)d_in[5];
    float* out = (float*)d_out;
    (void)in_sizes; (void)n_in; (void)out_size;

    cudaFuncSetAttribute(p4, cudaFuncAttributeMaxDynamicSharedMemorySize, P4_SMEM);
    cudaFuncSetAttribute(p5, cudaFuncAttributeMaxDynamicSharedMemorySize, P5_SMEM);

    k0<<<64, 256>>>(mux0, mux1, mux2);
    p1<<<dim3(4, 512), NT, P1_SMEM>>>(images);
    p2<<<dim3(8, 512), NT, P2_SMEM>>>();
    p3<<<dim3(8, 512), NT, P3_SMEM>>>();
    p4<<<dim3(4, 512), NT, P4_SMEM>>>();
    p5<<<512, NT, P5_SMEM>>>(W, bias, out);
}

// round 3
// speedup vs baseline: 1.5408x; 1.5408x over previous
#include <cuda_runtime.h>
#include <math.h>

#define PI_D 3.14159265358979323846

// ---------------- static device scratch ----------------
__device__ float2 g_S[512 * 2 * 128 * 128];   // state [b][f][X][Y]
__device__ float4 g_U0[128 * 128 * 2];        // mux0 unitaries, bitrev-permuted
__device__ float4 g_U1[2 * 2 * 64 * 64 * 2];
__device__ float4 g_U2[2 * 2 * 32 * 32 * 2];
__device__ float2 g_TW[64];                   // exp(-2*pi*i*t/128)
__device__ int    g_NR[128];                  // bitrev-domain negation table
__device__ float  g_part[512 * 2 * 10];       // partial logits per (b, xc1)

__device__ __forceinline__ float2 cmul(float2 a, float2 b) {
    return make_float2(a.x * b.x - a.y * b.y, a.x * b.y + a.y * b.x);
}
__device__ __forceinline__ float2 cmulc(float2 a, float2 b) {  // a * conj(b)
    return make_float2(a.x * b.x + a.y * b.y, a.y * b.x - a.x * b.y);
}

// ---------------- register-blocked radix-2 FFT engine ----------------
// element (line, p) at base[ (line & (2^LG1-1))*SL1 + (line>>LG1)*SL2 + p*SP ]
// FWD: DIF natural->bitrev, tw exp(-2pi i t / 2^{s+1}); INV: DIT bitrev->natural,
// conj twiddles, scale folded into final pass. Two stages per smem pass.
template<bool INV, int NTT, int SP, int SL1, int LG1, int SL2, int LG2, int LOGN>
__device__ __forceinline__ void fft_run(float2* __restrict__ base,
                                        const float2* __restrict__ tw, float scale)
{
    constexpr int L = 1 << (LG1 + LG2);
    constexpr int N = 1 << LOGN;
    constexpr int ITEM2 = L * (N >> 2);
    constexpr int ITEM1 = L * (N >> 1);
    if constexpr (!INV) {
        #pragma unroll
        for (int s = LOGN - 1; s >= 1; s -= 2) {
            const int slo = s - 1;
            const int h = 1 << slo;
            for (int u = threadIdx.x; u < ITEM2; u += NTT) {
                const int line = u & (L - 1);
                const int loff = (line & ((1 << LG1) - 1)) * SL1 + (line >> LG1) * SL2;
                const int v = u >> (LG1 + LG2);
                const int t = v & (h - 1);
                const int p = ((v >> slo) << (slo + 2)) + t;
                float2* e = base + loff + p * SP;
                float2 a = e[0], b = e[h * SP], c = e[2 * h * SP], d = e[3 * h * SP];
                const float2 w0 = tw[t << (5 - slo)];                 // W(t, 4h)
                const float2 w1 = make_float2(w0.y, -w0.x);           // W(t+h, 4h) = w0*(-i)
                const float2 w2 = make_float2(w0.x * w0.x - w0.y * w0.y,
                                              2.f * w0.x * w0.y);     // W(t, 2h) = w0^2
                float2 ac = make_float2(a.x + c.x, a.y + c.y);
                float2 bd = make_float2(b.x + d.x, b.y + d.y);
                float2 cP = cmul(make_float2(a.x - c.x, a.y - c.y), w0);
                float2 dP = cmul(make_float2(b.x - d.x, b.y - d.y), w1);
                e[0]          = make_float2(ac.x + bd.x, ac.y + bd.y);
                e[h * SP]     = cmul(make_float2(ac.x - bd.x, ac.y - bd.y), w2);
                e[2 * h * SP] = make_float2(cP.x + dP.x, cP.y + dP.y);
                e[3 * h * SP] = cmul(make_float2(cP.x - dP.x, cP.y - dP.y), w2);
            }
            __syncthreads();
        }
        if constexpr (LOGN & 1) {   // leftover stage s=0, twiddle = 1
            for (int u = threadIdx.x; u < ITEM1; u += NTT) {
                const int line = u & (L - 1);
                const int loff = (line & ((1 << LG1) - 1)) * SL1 + (line >> LG1) * SL2;
                const int v = u >> (LG1 + LG2);
                float2* e = base + loff + (v << 1) * SP;
                float2 a = e[0], b = e[SP];
                e[0]  = make_float2(a.x + b.x, a.y + b.y);
                e[SP] = make_float2(a.x - b.x, a.y - b.y);
            }
            __syncthreads();
        }
    } else {
        #pragma unroll
        for (int s = 0; s + 1 <= LOGN - 1; s += 2) {
            const int h = 1 << s;
            const bool last = (s + 1 == LOGN - 1);
            const float sc = last ? scale : 1.f;
            for (int u = threadIdx.x; u < ITEM2; u += NTT) {
                const int line = u & (L - 1);
                const int loff = (line & ((1 << LG1) - 1)) * SL1 + (line >> LG1) * SL2;
                const int v = u >> (LG1 + LG2);
                const int t = v & (h - 1);
                const int p = ((v >> s) << (s + 2)) + t;
                float2* e = base + loff + p * SP;
                float2 a = e[0], b = e[h * SP], c = e[2 * h * SP], d = e[3 * h * SP];
                const float2 w0 = tw[t << (5 - s)];                   // W(t, 4h)
                const float2 w1 = make_float2(w0.y, -w0.x);
                const float2 w2 = make_float2(w0.x * w0.x - w0.y * w0.y,
                                              2.f * w0.x * w0.y);     // W(t, 2h)
                float2 bw = cmulc(b, w2), dw = cmulc(d, w2);
                float2 aP = make_float2(a.x + bw.x, a.y + bw.y);
                float2 bP = make_float2(a.x - bw.x, a.y - bw.y);
                float2 cP = make_float2(c.x + dw.x, c.y + dw.y);
                float2 dP = make_float2(c.x - dw.x, c.y - dw.y);
                float2 cw = cmulc(cP, w0), dq = cmulc(dP, w1);
                e[0]          = make_float2((aP.x + cw.x) * sc, (aP.y + cw.y) * sc);
                e[2 * h * SP] = make_float2((aP.x - cw.x) * sc, (aP.y - cw.y) * sc);
                e[h * SP]     = make_float2((bP.x + dq.x) * sc, (bP.y + dq.y) * sc);
                e[3 * h * SP] = make_float2((bP.x - dq.x) * sc, (bP.y - dq.y) * sc);
            }
            __syncthreads();
        }
        if constexpr (LOGN & 1) {   // leftover stage s = LOGN-1, has the scale
            constexpr int s = LOGN - 1;
            constexpr int h = 1 << s;
            for (int u = threadIdx.x; u < ITEM1; u += NTT) {
                const int line = u & (L - 1);
                const int loff = (line & ((1 << LG1) - 1)) * SL1 + (line >> LG1) * SL2;
                const int t = u >> (LG1 + LG2);   // p = t for the last stage
                float2* e = base + loff + t * SP;
                float2 a = e[0], b = e[h * SP];
                const float2 w = tw[t << (6 - s)];
                float2 bw = cmulc(b, w);
                e[0]      = make_float2((a.x + bw.x) * scale, (a.y + bw.y) * scale);
                e[h * SP] = make_float2((a.x - bw.x) * scale, (a.y - bw.y) * scale);
            }
            __syncthreads();
        }
    }
}

__device__ __forceinline__ void apply_mux(float2& p0, float2& p1, float4 uA, float4 uB) {
    float2 o0, o1;
    o0.x = uA.x * p0.x - uA.y * p0.y + uA.z * p1.x - uA.w * p1.y;
    o0.y = uA.x * p0.y + uA.y * p0.x + uA.z * p1.y + uA.w * p1.x;
    o1.x = uB.x * p0.x - uB.y * p0.y + uB.z * p1.x - uB.w * p1.y;
    o1.y = uB.x * p0.y + uB.y * p0.x + uB.z * p1.y + uB.w * p1.x;
    p0 = o0; p1 = o1;
}

// ---------------- K0: precompute ----------------
__device__ __forceinline__ void writeU(float4* dst, float axf, float ayf, float azf) {
    double ax = axf, ay = ayf, az = azf;
    double r = sqrt(ax * ax + ay * ay + az * az + 1e-20);
    double cr = cos(r), sn = sin(r) / r;
    dst[0] = make_float4((float)cr, (float)(-az * sn), (float)(-ay * sn), (float)(-ax * sn));
    dst[1] = make_float4((float)(ay * sn), (float)(-ax * sn), (float)cr, (float)(az * sn));
}

__global__ void k0(const float* __restrict__ mux0, const float* __restrict__ mux1,
                   const float* __restrict__ mux2) {
    int idx = blockIdx.x * blockDim.x + threadIdx.x;   // 16384 threads
    if (idx < 64) {
        double ang = -2.0 * PI_D * (double)idx / 128.0;
        g_TW[idx] = make_float2((float)cos(ang), (float)sin(ang));
    }
    if (idx < 128) {
        int k = __brev((unsigned)idx) >> 25;
        g_NR[idx] = (int)(__brev((unsigned)((128 - k) & 127)) >> 25);
    }
    {
        int kxb = idx >> 7, kyb = idx & 127;
        int kx = __brev((unsigned)kxb) >> 25, ky = __brev((unsigned)kyb) >> 25;
        const float* c = mux0 + (kx * 128 + ky) * 3;
        writeU(&g_U0[idx * 2], c[0], c[1], c[2]);
    }
    {
        int cx = idx >> 13, cy = (idx >> 12) & 1, kxb = (idx >> 6) & 63, kyb = idx & 63;
        int kx = __brev((unsigned)kxb) >> 26, ky = __brev((unsigned)kyb) >> 26;
        const float* c = mux1 + (((cx * 2 + cy) * 64 + kx) * 64 + ky) * 3;
        writeU(&g_U1[idx * 2], c[0], c[1], c[2]);
    }
    if (idx < 4096) {
        int cx = idx >> 11, cy = (idx >> 10) & 1, kxb = (idx >> 5) & 31, kyb = idx & 31;
        int kx = __brev((unsigned)kxb) >> 27, ky = __brev((unsigned)kyb) >> 27;
        const float* c = mux2 + (((cx * 2 + cy) * 32 + kx) * 32 + ky) * 3;
        writeU(&g_U2[idx * 2], c[0], c[1], c[2]);
    }
}

// ---------------- P1: encode + y-FFT128 (Hermitian packed) ----------------
#define NT1 512
__global__ __launch_bounds__(NT1) void p1(const float* __restrict__ images) {
    __shared__ float2 z[128 * 33];
    __shared__ float2 tw[64];
    const int b = blockIdx.y, X0 = blockIdx.x * 32;
    for (int i = threadIdx.x; i < 64; i += NT1) tw[i] = g_TW[i];
    for (int idx = threadIdx.x; idx < 4096; idx += NT1) {
        int l = idx >> 7, y = idx & 127;
        float I = images[(b * 128 + X0 + l) * 128 + y];
        float sv, cv;
        sincosf(0.5f * (float)PI_D * I, &sv, &cv);
        z[y * 33 + l] = make_float2(cv * (1.0f / 128.0f), sv * (1.0f / 128.0f));
    }
    __syncthreads();
    fft_run<false, NT1, 33, 1, 5, 0, 0, 7>(z, tw, 1.f);
    for (int idx = threadIdx.x; idx < 4096; idx += NT1) {
        int l = idx >> 7, kb = idx & 127;
        float2 Z = z[kb * 33 + l];
        float2 Zn = z[g_NR[kb] * 33 + l];
        float2 C  = make_float2(0.5f * (Z.x + Zn.x), 0.5f * (Z.y - Zn.y));
        float2 Sf = make_float2(0.5f * (Z.y + Zn.y), 0.5f * (Zn.x - Z.x));
        int X = X0 + l;
        g_S[((b * 2 + 0) * 128 + X) * 128 + kb] = C;
        g_S[((b * 2 + 1) * 128 + X) * 128 + kb] = Sf;
    }
}

// ---------------- P2: x-FFT128 + mux0 + x-IFFT128 + x-FFT64(halves) ----------------
#define NT2 512
__global__ __launch_bounds__(NT2) void p2() {
    __shared__ float2 tile[2 * 128 * 16];
    __shared__ float2 tw[64];
    const int b = blockIdx.y, y0 = blockIdx.x * 16;
    for (int i = threadIdx.x; i < 64; i += NT2) tw[i] = g_TW[i];
    for (int idx = threadIdx.x; idx < 4096; idx += NT2) {
        int yl = idx & 15, X = (idx >> 4) & 127, f = idx >> 11;
        tile[f * 2048 + X * 16 + yl] = g_S[((b * 2 + f) * 128 + X) * 128 + y0 + yl];
    }
    __syncthreads();
    fft_run<false, NT2, 16, 1, 4, 2048, 1, 7>(tile, tw, 1.f);
    for (int idx = threadIdx.x; idx < 2048; idx += NT2) {
        int yl = idx & 15, kxb = idx >> 4;
        int off = kxb * 16 + yl;
        float2 q0 = tile[off], q1 = tile[2048 + off];
        int ui = ((kxb << 7) + y0 + yl) * 2;
        apply_mux(q0, q1, g_U0[ui], g_U0[ui + 1]);
        tile[off] = q0; tile[2048 + off] = q1;
    }
    __syncthreads();
    fft_run<true,  NT2, 16, 1, 4, 2048, 1, 7>(tile, tw, 1.0f / 128.0f);
    fft_run<false, NT2, 16, 1, 4, 1024, 2, 6>(tile, tw, 1.f);   // halves x planes
    for (int idx = threadIdx.x; idx < 4096; idx += NT2) {
        int yl = idx & 15, X = (idx >> 4) & 127, f = idx >> 11;
        g_S[((b * 2 + f) * 128 + X) * 128 + y0 + yl] = tile[f * 2048 + X * 16 + yl];
    }
}

// ---------------- P35: y-junction + mux1 + x-junction + y-junction + mux2
//                   + final IFFT32s + measure + partial GEMV ----------------
#define NT3 1024
#define P35_SMEM (132096 + 512 + 8192 + 1280)
__global__ __launch_bounds__(NT3) void p35(const float* __restrict__ W) {
    extern __shared__ char sm[];
    float2* tile = (float2*)sm;                            // [2][64][129]
    float2* tw   = (float2*)(sm + 132096);
    float*  prob = (float*)(sm + 132096 + 512);            // 2048 f32
    float*  red  = (float*)(sm + 132096 + 512 + 8192);     // 32*10 f32
    const int b = blockIdx.y, xc1 = blockIdx.x;
    for (int i = threadIdx.x; i < 64; i += NT3) tw[i] = g_TW[i];
    for (int idx = threadIdx.x; idx < 16384; idx += NT3) {
        int Y = idx & 127, X = (idx >> 7) & 63, f = idx >> 13;
        tile[f * 8256 + X * 129 + Y] = g_S[((b * 2 + f) * 128 + xc1 * 64 + X) * 128 + Y];
    }
    __syncthreads();
    // y junction 128->64
    fft_run<true,  NT3, 1, 129, 7, 0,  0, 7>(tile, tw, 1.0f / 128.0f);
    fft_run<false, NT3, 1, 129, 7, 64, 1, 6>(tile, tw, 1.f);
    // mux1
    for (int idx = threadIdx.x; idx < 8192; idx += NT3) {
        int Y = idx & 127, X = idx >> 7;
        int off = X * 129 + Y;
        float2 q0 = tile[off], q1 = tile[8256 + off];
        int yc1 = Y >> 6, Yb = Y & 63;
        int ui = (((xc1 * 2 + yc1) << 12) + (X << 6) + Yb) * 2;
        apply_mux(q0, q1, g_U1[ui], g_U1[ui + 1]);
        tile[off] = q0; tile[8256 + off] = q1;
    }
    __syncthreads();
    // x junction 64->32, then y junction 64->32
    fft_run<true,  NT3, 129, 1, 7, 8256, 1, 6>(tile, tw, 1.0f / 64.0f);
    fft_run<false, NT3, 129, 1, 7, 4128, 2, 5>(tile, tw, 1.f);
    fft_run<true,  NT3, 1, 129, 7, 64, 1, 6>(tile, tw, 1.0f / 64.0f);
    fft_run<false, NT3, 1, 129, 7, 32, 2, 5>(tile, tw, 1.f);
    // mux2
    for (int idx = threadIdx.x; idx < 8192; idx += NT3) {
        int Y = idx & 127, X = idx >> 7;
        int off = X * 129 + Y;
        float2 q0 = tile[off], q1 = tile[8256 + off];
        int xc2 = X >> 5, yc2 = (Y >> 5) & 1;
        int ui = (((xc2 * 2 + yc2) << 10) + ((X & 31) << 5) + (Y & 31)) * 2;
        apply_mux(q0, q1, g_U2[ui], g_U2[ui + 1]);
        tile[off] = q0; tile[8256 + off] = q1;
    }
    __syncthreads();
    // final iqft2d (32-point both axes)
    fft_run<true, NT3, 129, 1, 7, 4128, 2, 5>(tile, tw, 1.0f / 32.0f);
    fft_run<true, NT3, 1, 129, 7, 32,   2, 5>(tile, tw, 1.0f / 32.0f);
    // measurement: partial prob over (xc2, yc1, yc2)
    for (int idx = threadIdx.x; idx < 2048; idx += NT3) {
        int f = idx & 1, ya = (idx >> 1) & 31, xa = idx >> 6;
        float s = 0.f;
        #pragma unroll
        for (int xc2 = 0; xc2 < 2; ++xc2)
            #pragma unroll
            for (int yq = 0; yq < 4; ++yq) {
                float2 v = tile[f * 8256 + (xc2 * 32 + xa) * 129 + yq * 32 + ya];
                s += v.x * v.x + v.y * v.y;
            }
        prob[idx] = s;
    }
    __syncthreads();
    // partial GEMV
    float acc[10];
    #pragma unroll
    for (int c = 0; c < 10; ++c) acc[c] = 0.f;
    {
        int j0 = threadIdx.x * 2;
        float2 pv = *(const float2*)(prob + j0);
        #pragma unroll
        for (int c = 0; c < 10; ++c) {
            float2 wv = *(const float2*)(W + c * 2048 + j0);
            acc[c] = fmaf(pv.x, wv.x, fmaf(pv.y, wv.y, acc[c]));
        }
    }
    #pragma unroll
    for (int c = 0; c < 10; ++c)
        #pragma unroll
        for (int o = 16; o > 0; o >>= 1)
            acc[c] += __shfl_down_sync(0xffffffffu, acc[c], o);
    const int warp = threadIdx.x >> 5, lane = threadIdx.x & 31;
    if (lane == 0)
        #pragma unroll
        for (int c = 0; c < 10; ++c) red[warp * 10 + c] = acc[c];
    __syncthreads();
    if (threadIdx.x < 10) {
        float s = 0.f;
        #pragma unroll
        for (int w = 0; w < 32; ++w) s += red[w * 10 + threadIdx.x];
        g_part[(b * 2 + xc1) * 10 + threadIdx.x] = s;
    }
}

// ---------------- combine ----------------
__global__ void pc(const float* __restrict__ bias, float* __restrict__ out) {
    int i = blockIdx.x * blockDim.x + threadIdx.x;
    if (i < 5120) {
        int b = i / 10, c = i % 10;
        out[i] = bias[c] + g_part[(b * 2) * 10 + c] + g_part[(b * 2 + 1) * 10 + c];
    }
}

// ---------------- launch ----------------
extern "C" void kernel_launch(void* const* d_in, const int* in_sizes, int n_in,
                              void* d_out, int out_size) {
    const float* images = (const float*)d_in[0];
    const float* mux0 = (const float*)d_in[1];
    const float* mux1 = (const float*)d_in[2];
    const float* mux2 = (const float*)d_in[3];
    const float* W = (const float*)d_in[4];
    const float* bias = (const float*)d_in[5];
    float* out = (float*)d_out;
    (void)in_sizes; (void)n_in; (void)out_size;

    cudaFuncSetAttribute(p35, cudaFuncAttributeMaxDynamicSharedMemorySize, P35_SMEM);

    k0<<<64, 256>>>(mux0, mux1, mux2);
    p1<<<dim3(4, 512), NT1>>>(images);
    p2<<<dim3(8, 512), NT2>>>();
    p35<<<dim3(2, 512), NT3, P35_SMEM>>>(W);
    pc<<<10, 512>>>(bias, out);
}